// round 1
// baseline (speedup 1.0000x reference)
#include <cuda_runtime.h>
#include <cstdint>

#define NN   8192
#define IND  128
#define OUTD 64

// static device scratch (no allocations allowed)
__device__ float g_Wh[(size_t)NN * OUTD];
__device__ float g_s1[NN];
__device__ float g_s2[NN];

__device__ __forceinline__ unsigned long long pk2(float lo, float hi) {
    unsigned long long r;
    asm("mov.b64 %0, {%1, %2};" : "=l"(r) : "f"(lo), "f"(hi));
    return r;
}
__device__ __forceinline__ void ffma2(unsigned long long& d, unsigned long long a, unsigned long long b) {
    asm("fma.rn.f32x2 %0, %1, %2, %0;" : "+l"(d) : "l"(a), "l"(b));
}
__device__ __forceinline__ float2 upk2(unsigned long long v) {
    float2 r;
    asm("mov.b64 {%0, %1}, %2;" : "=f"(r.x), "=f"(r.y) : "l"(v));
    return r;
}

// ---------------------------------------------------------------------------
// K1: Wh = x @ W   [8192,64];  s1 = Wh @ a[:64];  s2 = Wh @ a[64:]
// grid 256 blocks x 128 threads, 32 rows/block.
// thread tile: 4 rows x 4 dims. dim_lane = t%16, row_lane = t/16.
// ---------------------------------------------------------------------------
__global__ __launch_bounds__(128) void k1_proj(const float* __restrict__ x,
                                               const float* __restrict__ W,
                                               const float* __restrict__ a) {
    __shared__ float W_sm[IND][OUTD];   // 32 KB, same layout as gmem
    __shared__ float x_sm[32][33];      // padded

    const int t  = threadIdx.x;
    const int i0 = blockIdx.x * 32;
    const int dl = t & 15;   // dims dl*4 .. dl*4+3
    const int rl = t >> 4;   // rows rl*4 .. rl*4+3

    // load W into smem (flat copy)
    {
        const float4* src = (const float4*)W;
        float4* dst = (float4*)&W_sm[0][0];
#pragma unroll
        for (int q = 0; q < 16; ++q) dst[t + 128 * q] = src[t + 128 * q];
    }

    float acc[4][4];
#pragma unroll
    for (int rr = 0; rr < 4; ++rr)
#pragma unroll
        for (int dd = 0; dd < 4; ++dd) acc[rr][dd] = 0.f;

    for (int k0 = 0; k0 < IND; k0 += 32) {
        __syncthreads();
#pragma unroll
        for (int q = 0; q < 8; ++q) {
            int idx = t + 128 * q;           // 0..1023
            int r = idx >> 5, kk = idx & 31;
            x_sm[r][kk] = x[(size_t)(i0 + r) * IND + k0 + kk];
        }
        __syncthreads();
#pragma unroll
        for (int kk = 0; kk < 32; ++kk) {
            float4 w = *(const float4*)&W_sm[k0 + kk][dl * 4];
#pragma unroll
            for (int rr = 0; rr < 4; ++rr) {
                float xv = x_sm[rl * 4 + rr][kk];
                acc[rr][0] += xv * w.x;
                acc[rr][1] += xv * w.y;
                acc[rr][2] += xv * w.z;
                acc[rr][3] += xv * w.w;
            }
        }
    }

    const float* a1 = a;
    const float* a2 = a + OUTD;
#pragma unroll
    for (int rr = 0; rr < 4; ++rr) {
        int row = i0 + rl * 4 + rr;
        *(float4*)&g_Wh[(size_t)row * OUTD + dl * 4] =
            make_float4(acc[rr][0], acc[rr][1], acc[rr][2], acc[rr][3]);
        float4 av1 = *(const float4*)&a1[dl * 4];
        float4 av2 = *(const float4*)&a2[dl * 4];
        float v1 = acc[rr][0] * av1.x + acc[rr][1] * av1.y + acc[rr][2] * av1.z + acc[rr][3] * av1.w;
        float v2 = acc[rr][0] * av2.x + acc[rr][1] * av2.y + acc[rr][2] * av2.z + acc[rr][3] * av2.w;
#pragma unroll
        for (int o = 8; o >= 1; o >>= 1) {
            v1 += __shfl_xor_sync(0xffffffffu, v1, o, 16);
            v2 += __shfl_xor_sync(0xffffffffu, v2, o, 16);
        }
        if (dl == 0) { g_s1[row] = v1; g_s2[row] = v2; }
    }
}

// ---------------------------------------------------------------------------
// K2: fused attention. One pass over adj (no online max needed: scores bounded,
// masked score = -1e12 -> exp underflows to exactly 0, matching the reference).
// grid 256 blocks x 64 threads, 32 rows/block, j tiled by 64.
// FMA layout: dim_lane = t%8 (8 dims), row_lane = t/8 (4 rows) -> 4x8 thread
// tile, f32x2 packed FMA.
// p-compute layout: p_row = t/2, 32-column half = t%2 (coalesced adj stream,
// per-thread partial row-sum l accumulates for free).
// ---------------------------------------------------------------------------
__global__ __launch_bounds__(64) void k2_attn(const int* __restrict__ adj,
                                              float* __restrict__ out) {
    __shared__ float Wh_sm[64][68];   // pad 68: 2-way max conflicts
    __shared__ float p_sm[32][68];
    __shared__ float lpart[64];
    __shared__ float l_sm[32];

    const int t  = threadIdx.x;
    const int i0 = blockIdx.x * 32;
    const int dl = t & 7;    // dims dl*8 .. dl*8+7
    const int rl = t >> 3;   // rows rl*4 .. rl*4+3
    const int pr = t >> 1;   // p-compute row (0..31)
    const int pc = (t & 1) * 32;

    const float s1v = g_s1[i0 + pr];
    const int* adjrow = adj + (size_t)(i0 + pr) * NN + pc;

    float lacc = 0.f;
    unsigned long long acc[4][4];
#pragma unroll
    for (int rr = 0; rr < 4; ++rr)
#pragma unroll
        for (int q = 0; q < 4; ++q) acc[rr][q] = 0ull;

    for (int tile = 0; tile < NN / 64; ++tile) {
        const int j0 = tile * 64;
        __syncthreads();   // protect previous tile's smem reads

        // load Wh tile: thread t owns row j0+t
        {
            const float4* src = (const float4*)(g_Wh + (size_t)(j0 + t) * OUTD);
#pragma unroll
            for (int q = 0; q < 16; ++q) *(float4*)&Wh_sm[t][4 * q] = src[q];
        }
        // compute p tile (reads adj coalesced, s2 via L1)
        {
            const int4*   a4p = (const int4*)(adjrow + j0);
            const float4* s4p = (const float4*)(g_s2 + j0 + pc);
#pragma unroll
            for (int k = 0; k < 8; ++k) {
                int4   a4 = a4p[k];
                float4 s4 = s4p[k];
                float4 pv;
                float e;
                e = s1v + s4.x; e = e > 0.f ? e : 0.2f * e; pv.x = a4.x ? __expf(e) : 0.f;
                e = s1v + s4.y; e = e > 0.f ? e : 0.2f * e; pv.y = a4.y ? __expf(e) : 0.f;
                e = s1v + s4.z; e = e > 0.f ? e : 0.2f * e; pv.z = a4.z ? __expf(e) : 0.f;
                e = s1v + s4.w; e = e > 0.f ? e : 0.2f * e; pv.w = a4.w ? __expf(e) : 0.f;
                lacc += (pv.x + pv.y) + (pv.z + pv.w);
                *(float4*)&p_sm[pr][pc + 4 * k] = pv;
            }
        }
        __syncthreads();

        // accumulate: acc[r][d] += p[r][j] * Wh[j][d]
        for (int jb = 0; jb < 64; jb += 4) {
            float4 pq[4];
#pragma unroll
            for (int rr = 0; rr < 4; ++rr) pq[rr] = *(const float4*)&p_sm[rl * 4 + rr][jb];
#pragma unroll
            for (int m = 0; m < 4; ++m) {
                const int j = jb + m;
                float4 w0 = *(const float4*)&Wh_sm[j][dl * 8];
                float4 w1 = *(const float4*)&Wh_sm[j][dl * 8 + 4];
                unsigned long long wl0 = pk2(w0.x, w0.y);
                unsigned long long wl1 = pk2(w0.z, w0.w);
                unsigned long long wl2 = pk2(w1.x, w1.y);
                unsigned long long wl3 = pk2(w1.z, w1.w);
#pragma unroll
                for (int rr = 0; rr < 4; ++rr) {
                    float pv = (m == 0) ? pq[rr].x : (m == 1) ? pq[rr].y : (m == 2) ? pq[rr].z : pq[rr].w;
                    unsigned long long pp = pk2(pv, pv);
                    ffma2(acc[rr][0], wl0, pp);
                    ffma2(acc[rr][1], wl1, pp);
                    ffma2(acc[rr][2], wl2, pp);
                    ffma2(acc[rr][3], wl3, pp);
                }
            }
        }
    }

    // reduce l across the two half-row threads
    lpart[t] = lacc;
    __syncthreads();
    if (t < 32) l_sm[t] = lpart[2 * t] + lpart[2 * t + 1];
    __syncthreads();

    // normalize + ELU + store
#pragma unroll
    for (int rr = 0; rr < 4; ++rr) {
        const int r = rl * 4 + rr;
        const float inv = 1.0f / l_sm[r];
        float o[8];
#pragma unroll
        for (int q = 0; q < 4; ++q) {
            float2 v = upk2(acc[rr][q]);
            o[2 * q]     = v.x * inv;
            o[2 * q + 1] = v.y * inv;
        }
#pragma unroll
        for (int q = 0; q < 8; ++q) { float v = o[q]; o[q] = v > 0.f ? v : expm1f(v); }
        float4* dst = (float4*)&out[(size_t)(i0 + r) * OUTD + dl * 8];
        dst[0] = make_float4(o[0], o[1], o[2], o[3]);
        dst[1] = make_float4(o[4], o[5], o[6], o[7]);
    }
}

extern "C" void kernel_launch(void* const* d_in, const int* in_sizes, int n_in,
                              void* d_out, int out_size) {
    const float* x   = (const float*)d_in[0];
    const int*   adj = (const int*)d_in[1];
    const float* W   = (const float*)d_in[2];
    const float* a   = (const float*)d_in[3];
    float* out = (float*)d_out;

    k1_proj<<<256, 128>>>(x, W, a);
    k2_attn<<<256, 64>>>(adj, out);
}